// round 12
// baseline (speedup 1.0000x reference)
#include <cuda_runtime.h>
#include <math.h>

// ---------------- problem constants ----------------
#define NYI   300
#define NXI   300
#define PML_W 20
#define NYP   340
#define NXP   340
#define NT    128
#define NSHOT 2
#define NREC  32
#define DT_F    0.001f
#define INV_DX  0.2f
#define C1F     1.125f
#define C2F     (-1.0f/24.0f)

// ---------------- tiling: 16x8 tiles per shot, 2 CTAs per SM ----------------
#define TSY   16
#define TSX   8
#define TILEY 22
#define TILEX 43
#define NB    (NSHOT*TSY*TSX)         // 256 CTAs
#define NTHR  256
#define SP    52                      // even smem row pitch (8B pair alignment)
#define SROWS (TILEY+4)               // 26
#define FSZ   (SROWS*SP)              // 1352 floats per field
#define NFS   17
#define SMEM_BYTES (NFS*FSZ*4)        // 91936 B (2 per SM)

enum {F_VY=0,F_VX,F_SYY,F_SXX,F_SXY,F_MVYY,F_MVYX,F_MVXY,F_MVXX,
      F_MSYYY,F_MSXYX,F_MSXYY,F_MSXXX,F_BUO,F_LAM,F_LP2M,F_MU};

// ---------------- exchange buffers ----------------
// layout: [cta][side(0N,1S,2W,3E)][field slot 0..4][2][43]
#define XLEN  (4*5*2*43)
__device__ float g_xch[NB*XLEN];
__device__ int   g_flag[NB*32];       // 128B padding per flag

#define XPTR(cta, side, f) (g_xch + (((cta)*4 + (side))*5 + (f))*86)
#define FLAG(cta) (g_flag[(cta)*32])

__global__ void k_init()
{
    if (threadIdx.x < NB) FLAG(threadIdx.x) = 0;
}

__device__ __forceinline__ float pml_b(int u)
{
    double d0 = 414.4653366865718;
    double lo = (20.0 - (double)u) / 20.0; lo = lo < 0.0 ? 0.0 : (lo > 1.0 ? 1.0 : lo);
    double hi = ((double)u - 319.0) / 20.0; hi = hi < 0.0 ? 0.0 : (hi > 1.0 ? 1.0 : hi);
    double mm = lo > hi ? lo : hi;
    return (float)exp(-d0 * mm * mm * 0.001);
}

__device__ __forceinline__ float2 lds2(const float* p){ return *(const float2*)p; }
__device__ __forceinline__ void   sts2(float* p, float2 v){ *(float2*)p = v; }

// ---------------- per-warp halo import ----------------
// NS: neighbor's opposing 2-row strip of one field into rows {baserow, baserow+1}
__device__ __forceinline__ void warp_read_NS_field(float* F, int nb, int nbside, int slot,
                                                   int baserow, int tw, int lane)
{
    const float* q = XPTR(nb, nbside, slot);
    for (int c = lane; c < tw; c += 32) F[ baserow   *SP + c + 2] = __ldcg(q + c);
    for (int c = lane; c < tw; c += 32) F[(baserow+1)*SP + c + 2] = __ldcg(q + 43 + c);
}
// WE: neighbor's opposing 2-col strip of one field into cols {basecol, basecol+1}
__device__ __forceinline__ void warp_read_WE_field(float* F, int nb, int nbside, int slot,
                                                   int basecol, int th, int lane)
{
    const float* q = XPTR(nb, nbside, slot);
    for (int r = lane; r < th; r += 32) F[(r+2)*SP + basecol    ] = __ldcg(q + r);
    for (int r = lane; r < th; r += 32) F[(r+2)*SP + basecol + 1] = __ldcg(q + 43 + r);
}

// ---------------- pair physics ----------------
// pf bits: 0 = lane1 valid (full pair), 1 = y-PML, 2 = x-PML, [3:4] src lane
__device__ __forceinline__ void pairV(int o, float by, float bx0, float bx1, int pf, float srcamp,
    float* SVY, float* SVX, const float* SSYY, const float* SSXX, const float* SSXY,
    float* SMSYYY, float* SMSXYX, float* SMSXYY, float* SMSXXX, const float* SBUO,
    float2& vy_o, float2& vx_o)
{
    const bool pY = pf & 2, pX = pf & 4;
    float2 A = lds2(SSYY+o+SP), B = lds2(SSYY+o), C = lds2(SSYY+o+2*SP), D = lds2(SSYY+o-SP);
    float2 t1;
    t1.x = (C1F*(A.x-B.x) + C2F*(C.x-D.x))*INV_DX;
    t1.y = (C1F*(A.y-B.y) + C2F*(C.y-D.y))*INV_DX;
    if (pY){
        float2 m = lds2(SMSYYY+o);
        m.x = by*m.x + (by-1.0f)*t1.x;  m.y = by*m.y + (by-1.0f)*t1.y;
        sts2(SMSYYY+o, m);  t1.x += m.x;  t1.y += m.y;
    }
    float2 xa = lds2(SSXY+o-2), xb = lds2(SSXY+o), xc = lds2(SSXY+o+2);
    float2 t2;
    t2.x = (C1F*(xb.x-xa.y) + C2F*(xb.y-xa.x))*INV_DX;
    t2.y = (C1F*(xb.y-xb.x) + C2F*(xc.x-xa.y))*INV_DX;
    if (pX){
        float2 m = lds2(SMSXYX+o);
        m.x = bx0*m.x + (bx0-1.0f)*t2.x;  m.y = bx1*m.y + (bx1-1.0f)*t2.y;
        sts2(SMSXYX+o, m);  t2.x += m.x;  t2.y += m.y;
    }
    float2 buo = lds2(SBUO+o);
    float2 vy  = lds2(SVY+o);
    vy.x += DT_F*buo.x*(t1.x+t2.x);
    vy.y += DT_F*buo.y*(t1.y+t2.y);
    const int sm_ = (pf >> 3) & 3;
    if (sm_ == 1) vy.x += srcamp;
    if (sm_ == 2) vy.y += srcamp;
    float2 yb = lds2(SSXY+o-SP), yc = lds2(SSXY+o+SP), yd = lds2(SSXY+o-2*SP);
    float2 t3;
    t3.x = (C1F*(xb.x-yb.x) + C2F*(yc.x-yd.x))*INV_DX;
    t3.y = (C1F*(xb.y-yb.y) + C2F*(yc.y-yd.y))*INV_DX;
    if (pY){
        float2 m = lds2(SMSXYY+o);
        m.x = by*m.x + (by-1.0f)*t3.x;  m.y = by*m.y + (by-1.0f)*t3.y;
        sts2(SMSXYY+o, m);  t3.x += m.x;  t3.y += m.y;
    }
    float2 ba = lds2(SSXX+o-2), bb = lds2(SSXX+o), bc = lds2(SSXX+o+2);
    float2 t4;
    t4.x = (C1F*(bb.y-bb.x) + C2F*(bc.x-ba.y))*INV_DX;
    t4.y = (C1F*(bc.x-bb.y) + C2F*(bc.y-bb.x))*INV_DX;
    if (pX){
        float2 m = lds2(SMSXXX+o);
        m.x = bx0*m.x + (bx0-1.0f)*t4.x;  m.y = bx1*m.y + (bx1-1.0f)*t4.y;
        sts2(SMSXXX+o, m);  t4.x += m.x;  t4.y += m.y;
    }
    float2 vx = lds2(SVX+o);
    vx.x += DT_F*buo.x*(t3.x+t4.x);
    vx.y += DT_F*buo.y*(t3.y+t4.y);
    if (pf & 1){ sts2(SVY+o, vy); sts2(SVX+o, vx); }
    else       { SVY[o] = vy.x;  SVX[o] = vx.x; }
    vy_o = vy; vx_o = vx;
}

__device__ __forceinline__ void pairS(int o, float by, float bx0, float bx1, int pf,
    const float* SVY, const float* SVX, float* SSYY, float* SSXX, float* SSXY,
    float* SMVYY, float* SMVYX, float* SMVXY, float* SMVXX,
    const float* SLAM, const float* SLP2M, const float* SMU,
    float2& syy_o, float2& sxx_o, float2& sxy_o)
{
    const bool pY = pf & 2, pX = pf & 4;
    float2 vb  = lds2(SVY+o);
    float2 vd1 = lds2(SVY+o-SP), vu1 = lds2(SVY+o+SP), vd2 = lds2(SVY+o-2*SP);
    float2 dyy;
    dyy.x = (C1F*(vb.x-vd1.x) + C2F*(vu1.x-vd2.x))*INV_DX;
    dyy.y = (C1F*(vb.y-vd1.y) + C2F*(vu1.y-vd2.y))*INV_DX;
    if (pY){
        float2 m = lds2(SMVYY+o);
        m.x = by*m.x + (by-1.0f)*dyy.x;  m.y = by*m.y + (by-1.0f)*dyy.y;
        sts2(SMVYY+o, m);  dyy.x += m.x;  dyy.y += m.y;
    }
    float2 xa = lds2(SVX+o-2), xb = lds2(SVX+o), xc = lds2(SVX+o+2);
    float2 dxx;
    dxx.x = (C1F*(xb.x-xa.y) + C2F*(xb.y-xa.x))*INV_DX;
    dxx.y = (C1F*(xb.y-xb.x) + C2F*(xc.x-xa.y))*INV_DX;
    if (pX){
        float2 m = lds2(SMVXX+o);
        m.x = bx0*m.x + (bx0-1.0f)*dxx.x;  m.y = bx1*m.y + (bx1-1.0f)*dxx.y;
        sts2(SMVXX+o, m);  dxx.x += m.x;  dxx.y += m.y;
    }
    float2 lam = lds2(SLAM+o), lp2m = lds2(SLP2M+o);
    float2 syy = lds2(SSYY+o), sxx = lds2(SSXX+o);
    syy.x += DT_F*(lp2m.x*dyy.x + lam.x*dxx.x);
    syy.y += DT_F*(lp2m.y*dyy.y + lam.y*dxx.y);
    sxx.x += DT_F*(lp2m.x*dxx.x + lam.x*dyy.x);
    sxx.y += DT_F*(lp2m.y*dxx.y + lam.y*dyy.y);
    float2 va = lds2(SVY+o-2), vc = lds2(SVY+o+2);
    float2 dyx;
    dyx.x = (C1F*(vb.y-vb.x) + C2F*(vc.x-va.y))*INV_DX;
    dyx.y = (C1F*(vc.x-vb.y) + C2F*(vc.y-vb.x))*INV_DX;
    if (pX){
        float2 m = lds2(SMVYX+o);
        m.x = bx0*m.x + (bx0-1.0f)*dyx.x;  m.y = bx1*m.y + (bx1-1.0f)*dyx.y;
        sts2(SMVYX+o, m);  dyx.x += m.x;  dyx.y += m.y;
    }
    float2 ua = lds2(SVX+o+SP), uc = lds2(SVX+o+2*SP), ud = lds2(SVX+o-SP);
    float2 dxy;
    dxy.x = (C1F*(ua.x-xb.x) + C2F*(uc.x-ud.x))*INV_DX;
    dxy.y = (C1F*(ua.y-xb.y) + C2F*(uc.y-ud.y))*INV_DX;
    if (pY){
        float2 m = lds2(SMVXY+o);
        m.x = by*m.x + (by-1.0f)*dxy.x;  m.y = by*m.y + (by-1.0f)*dxy.y;
        sts2(SMVXY+o, m);  dxy.x += m.x;  dxy.y += m.y;
    }
    float2 mu  = lds2(SMU+o);
    float2 sxy = lds2(SSXY+o);
    sxy.x += DT_F*mu.x*(dyx.x+dxy.x);
    sxy.y += DT_F*mu.y*(dyx.y+dxy.y);
    if (pf & 1){ sts2(SSYY+o, syy); sts2(SSXX+o, sxx); sts2(SSXY+o, sxy); }
    else       { SSYY[o] = syy.x;  SSXX[o] = sxx.x;  SSXY[o] = sxy.x; }
    syy_o = syy; sxx_o = sxx; sxy_o = sxy;
}

__global__ void __launch_bounds__(NTHR, 2)
k_main(const float* __restrict__ lamb,
       const float* __restrict__ muv,
       const float* __restrict__ buov,
       const float* __restrict__ amp,    // [NSHOT,1,NT]
       const int*   __restrict__ sloc,   // [NSHOT,1,2]
       const int*   __restrict__ rloc,   // [NSHOT,NREC,2]
       float*       __restrict__ out)    // [NSHOT,NREC,NT]
{
    extern __shared__ float sm[];
    const int tid  = threadIdx.x;
    const int lane = tid & 31;
    const int wid  = tid >> 5;
    const int me   = blockIdx.x;
    const int shot = me >> 7;
    const int tile = me & 127;
    const int ty   = tile >> 3, tx = tile & 7;
    const int y0   = ty * TILEY, x0 = tx * TILEX;
    const int th   = (y0 + TILEY <= NYP) ? TILEY : (NYP - y0);
    const int tw   = (x0 + TILEX <= NXP) ? TILEX : (NXP - x0);
    const bool hN = (ty > 0), hS = (ty < TSY-1), hW = (tx > 0), hE = (tx < TSX-1);

    float* SVY    = sm + F_VY   *FSZ;
    float* SVX    = sm + F_VX   *FSZ;
    float* SSYY   = sm + F_SYY  *FSZ;
    float* SSXX   = sm + F_SXX  *FSZ;
    float* SSXY   = sm + F_SXY  *FSZ;
    float* SMVYY  = sm + F_MVYY *FSZ;
    float* SMVYX  = sm + F_MVYX *FSZ;
    float* SMVXY  = sm + F_MVXY *FSZ;
    float* SMVXX  = sm + F_MVXX *FSZ;
    float* SMSYYY = sm + F_MSYYY*FSZ;
    float* SMSXYX = sm + F_MSXYX*FSZ;
    float* SMSXYY = sm + F_MSXYY*FSZ;
    float* SMSXXX = sm + F_MSXXX*FSZ;
    float* SBUO   = sm + F_BUO  *FSZ;
    float* SLAM   = sm + F_LAM  *FSZ;
    float* SLP2M  = sm + F_LP2M *FSZ;
    float* SMU    = sm + F_MU   *FSZ;

    for (int i = tid; i < 13*FSZ; i += NTHR) sm[i] = 0.0f;

    for (int i = tid; i < FSZ; i += NTHR){
        int lr = i / SP, lc = i - lr*SP;
        int gy = y0 - 2 + lr, gx = x0 - 2 + lc;
        int iy = gy - PML_W; iy = iy < 0 ? 0 : (iy > NYI-1 ? NYI-1 : iy);
        int ix = gx - PML_W; ix = ix < 0 ? 0 : (ix > NXI-1 ? NXI-1 : ix);
        float l = lamb[iy*NXI + ix];
        float m = muv [iy*NXI + ix];
        SBUO[i]  = buov[iy*NXI + ix];
        SLAM[i]  = l;
        SLP2M[i] = l + 2.0f*m;
        SMU[i]   = m;
    }

    const int sy = sloc[shot*2 + 0] + PML_W;
    const int sx = sloc[shot*2 + 1] + PML_W;

    const int npr = (tw + 1) >> 1;

    // frame pair (<=1/thread) + export records
    int fo = -1; float fby = 1.0f, fbx0 = 1.0f, fbx1 = 1.0f; int fpf = 0;
    int fnrec = 0; int frec[4] = {0,0,0,0};   // packed: idx<<2 | lane<<1 | kind(0=NS,1=WE)
    {
        const int nframe = 4*npr + (th-4)*3;
        if (tid < nframe){
            int row, p;
            if (tid < 2*npr){ row = tid / npr; p = tid % npr; }
            else if (tid < 4*npr){ int q = tid - 2*npr; row = th-2 + q / npr; p = q % npr; }
            else { int q = tid - 4*npr; row = 2 + q / 3; int j = q % 3; p = (j == 0) ? 0 : (npr - 3 + j); }
            int lc = 2*p, gy = y0 + row, gx = x0 + lc;
            fo  = (row+2)*SP + (lc+2);
            fby = pml_b(gy); fbx0 = pml_b(gx);
            bool full = (lc + 1 < tw);
            fbx1 = full ? pml_b(gx+1) : 1.0f;
            fpf = (full ? 1 : 0)
                | ((fby  != 1.0f) ? 2 : 0)
                | (((fbx0 != 1.0f) || (fbx1 != 1.0f)) ? 4 : 0);
            if (gy == sy){
                if (sx == gx) fpf |= (1 << 3);
                else if (full && sx == gx+1) fpf |= (2 << 3);
            }
            for (int ln = 0; ln < 2; ln++){
                int col = lc + ln;
                if (col >= tw) break;
                if (ln == 1 && !(fpf & 1)) break;
                if (hN && row < 2)
                    frec[fnrec++] = (((((me*4 + 0)*5)*86) + row*43 + col) << 2) | (ln << 1) | 0;
                if (hS && row >= th-2)
                    frec[fnrec++] = (((((me*4 + 1)*5)*86) + (row-(th-2))*43 + col) << 2) | (ln << 1) | 0;
                if (hW && col < 2)
                    frec[fnrec++] = (((((me*4 + 2)*5)*86) + col*43 + row) << 2) | (ln << 1) | 1;
                if (hE && col >= tw-2)
                    frec[fnrec++] = (((((me*4 + 3)*5)*86) + (col-(tw-2))*43 + row) << 2) | (ln << 1) | 1;
            }
        }
    }

    // interior pairs: pair0 -> idx = tid (all threads); pair1 -> top tids via idx = tid + n1
    int io[2] = {-1,-1}; float iby[2], ibx0[2], ibx1[2]; int ipf[2] = {0,0};
    {
        const int ppr = npr - 3;
        const int nint = (th-4) * ppr;
        const int n1 = nint - NTHR;            // count of pair1 work items (may be <=0)
#pragma unroll
        for (int k = 0; k < 2; k++){
            iby[k] = 1.0f; ibx0[k] = 1.0f; ibx1[k] = 1.0f;
            int idx = (k == 0) ? tid : (tid + (n1 > 0 ? n1 : -NTHR));
            bool valid = (k == 0) ? (idx < nint) : (n1 > 0 && idx >= NTHR && idx < nint);
            if (valid){
                int row = 2 + idx / ppr, p = 1 + idx % ppr;
                int lc = 2*p, gy = y0 + row, gx = x0 + lc;
                io[k]   = (row+2)*SP + (lc+2);
                iby[k]  = pml_b(gy); ibx0[k] = pml_b(gx); ibx1[k] = pml_b(gx+1);
                ipf[k] = 1
                    | ((iby[k]  != 1.0f) ? 2 : 0)
                    | (((ibx0[k] != 1.0f) || (ibx1[k] != 1.0f)) ? 4 : 0);
                if (gy == sy){
                    if (sx == gx) ipf[k] |= (1 << 3);
                    else if (sx == gx+1) ipf[k] |= (2 << 3);
                }
            }
        }
    }

    // comm-warp side assignment (warps 0..3 = N,S,W,E); these warps ALSO compute
    bool chas = false; int cnb = 0, cnbside = 0;
    if (wid == 0){ chas = hN; cnb = me - TSX; cnbside = 1; }
    if (wid == 1){ chas = hS; cnb = me + TSX; cnbside = 0; }
    if (wid == 2){ chas = hW; cnb = me - 1;   cnbside = 3; }
    if (wid == 3){ chas = hE; cnb = me + 1;   cnbside = 2; }

    // receiver ownership
    int rsoff = -1, rout = -1;
    if (tid < NSHOT*NREC){
        int rs = tid >> 5;
        int ry = rloc[tid*2 + 0] + PML_W;
        int rx = rloc[tid*2 + 1] + PML_W;
        if (rs == shot && ry >= y0 && ry < y0 + th && rx >= x0 && rx < x0 + tw){
            rsoff = (ry - y0 + 2)*SP + (rx - x0 + 2);
            rout  = tid*NT;
        }
    }
    __syncthreads();

    float2 dmy0, dmy1, dmy2;

    for (int t = 0; t < NT; t++){
        const float srcamp = amp[shot*NT + t];

        // ================= V phase =================
        if (fo >= 0){
            float2 vyv, vxv;
            pairV(fo, fby, fbx0, fbx1, fpf, srcamp, SVY, SVX, SSYY, SSXX, SSXY,
                  SMSYYY, SMSXYX, SMSXYY, SMSXXX, SBUO, vyv, vxv);
#pragma unroll
            for (int r = 0; r < 4; r++) if (r < fnrec){
                int pk = frec[r];
                int gi = pk >> 2;
                bool l1 = (pk & 2);
                g_xch[gi]      = l1 ? vyv.y : vyv.x;   // slot 0
                g_xch[gi + 86] = l1 ? vxv.y : vxv.x;   // slot 1
            }
        }
        __syncthreads();
        if (tid == 0){ __threadfence(); atomicExch(&FLAG(me), 2*t + 1); }

        if (io[0] >= 0)
            pairV(io[0], iby[0], ibx0[0], ibx1[0], ipf[0], srcamp, SVY, SVX, SSYY, SSXX, SSXY,
                  SMSYYY, SMSXYX, SMSXYY, SMSXXX, SBUO, dmy0, dmy1);

        if (wid < 4 && chas){
            if (lane == 0){ volatile int* f = &FLAG(cnb); while (*f < 2*t+1) {} }
            __syncwarp();
            if (wid < 2){
                int baserow = (wid == 0) ? 0 : th + 2;
                warp_read_NS_field(SVY, cnb, cnbside, 0, baserow, tw, lane);
                warp_read_NS_field(SVX, cnb, cnbside, 1, baserow, tw, lane);
            } else {
                int basecol = (wid == 2) ? 0 : tw + 2;
                warp_read_WE_field(SVY, cnb, cnbside, 0, basecol, th, lane);
                warp_read_WE_field(SVX, cnb, cnbside, 1, basecol, th, lane);
            }
        }
        if (io[1] >= 0)
            pairV(io[1], iby[1], ibx0[1], ibx1[1], ipf[1], srcamp, SVY, SVX, SSYY, SSXX, SSXY,
                  SMSYYY, SMSXYX, SMSXYY, SMSXXX, SBUO, dmy0, dmy1);
        __syncthreads();

        if (rout >= 0) out[rout + t] = SVY[rsoff];

        // ================= S phase =================
        if (fo >= 0){
            float2 syyv, sxxv, sxyv;
            pairS(fo, fby, fbx0, fbx1, fpf, SVY, SVX, SSYY, SSXX, SSXY,
                  SMVYY, SMVYX, SMVXY, SMVXX, SLAM, SLP2M, SMU, syyv, sxxv, sxyv);
#pragma unroll
            for (int r = 0; r < 4; r++) if (r < fnrec){
                int pk = frec[r];
                int gi = pk >> 2;
                bool l1 = (pk & 2);
                float sxyl = l1 ? sxyv.y : sxyv.x;
                if ((pk & 1) == 0){                      // NS side: syy (2) + sxy (4)
                    g_xch[gi + 172] = l1 ? syyv.y : syyv.x;
                    g_xch[gi + 344] = sxyl;
                } else {                                 // WE side: sxx (3) + sxy (4)
                    g_xch[gi + 258] = l1 ? sxxv.y : sxxv.x;
                    g_xch[gi + 344] = sxyl;
                }
            }
        }
        __syncthreads();
        if (tid == 0){ __threadfence(); atomicExch(&FLAG(me), 2*t + 2); }

        if (io[0] >= 0)
            pairS(io[0], iby[0], ibx0[0], ibx1[0], ipf[0], SVY, SVX, SSYY, SSXX, SSXY,
                  SMVYY, SMVYX, SMVXY, SMVXX, SLAM, SLP2M, SMU, dmy0, dmy1, dmy2);

        if (wid < 4 && chas){
            if (lane == 0){ volatile int* f = &FLAG(cnb); while (*f < 2*t+2) {} }
            __syncwarp();
            if (wid < 2){
                int baserow = (wid == 0) ? 0 : th + 2;
                warp_read_NS_field(SSYY, cnb, cnbside, 2, baserow, tw, lane);
                warp_read_NS_field(SSXY, cnb, cnbside, 4, baserow, tw, lane);
            } else {
                int basecol = (wid == 2) ? 0 : tw + 2;
                warp_read_WE_field(SSXX, cnb, cnbside, 3, basecol, th, lane);
                warp_read_WE_field(SSXY, cnb, cnbside, 4, basecol, th, lane);
            }
        }
        if (io[1] >= 0)
            pairS(io[1], iby[1], ibx0[1], ibx1[1], ipf[1], SVY, SVX, SSYY, SSXX, SSXY,
                  SMVYY, SMVYX, SMVXY, SMVXX, SLAM, SLP2M, SMU, dmy0, dmy1, dmy2);
        __syncthreads();
    }
}

// ---------------- launch ----------------
extern "C" void kernel_launch(void* const* d_in, const int* in_sizes, int n_in,
                              void* d_out, int out_size)
{
    const float* lamb = (const float*)d_in[0];
    const float* mu   = (const float*)d_in[1];
    const float* buo  = (const float*)d_in[2];
    const float* amp  = (const float*)d_in[3];
    const int*   sloc = (const int*)  d_in[4];
    const int*   rloc = (const int*)  d_in[5];
    float* out = (float*)d_out;

    cudaFuncSetAttribute(k_main, cudaFuncAttributeMaxDynamicSharedMemorySize, SMEM_BYTES);

    k_init<<<1, 256>>>();
    k_main<<<NB, NTHR, SMEM_BYTES>>>(lamb, mu, buo, amp, sloc, rloc, out);
}

// round 13
// speedup vs baseline: 1.4028x; 1.4028x over previous
#include <cuda_runtime.h>
#include <math.h>

// ---------------- problem constants ----------------
#define NYI   300
#define NXI   300
#define PML_W 20
#define NYP   340
#define NXP   340
#define NT    128
#define NSHOT 2
#define NREC  32
#define DT_F    0.001f
#define INV_DX  0.2f
#define C1F     1.125f
#define C2F     (-1.0f/24.0f)

// ---------------- tiling: 20x8 tiles per shot (17x43 cells), 3 CTAs per SM ----------------
#define TSY   20
#define TSX   8
#define TILEY 17
#define TILEX 43
#define NTPS  (TSY*TSX)               // 160 tiles per shot
#define NB    (NSHOT*NTPS)            // 320 CTAs
#define NTHR  256
#define SP    52                      // even smem row pitch (8B pair alignment)
#define SROWS (TILEY+4)               // 21
#define FSZ   (SROWS*SP)              // 1092 floats per field
#define NFS   17
#define SMEM_BYTES (NFS*FSZ*4)        // 74256 B (3 per SM fits 228KB)

enum {F_VY=0,F_VX,F_SYY,F_SXX,F_SXY,F_MVYY,F_MVYX,F_MVXY,F_MVXX,
      F_MSYYY,F_MSXYX,F_MSXYY,F_MSXXX,F_BUO,F_LAM,F_LP2M,F_MU};

// ---------------- exchange buffers ----------------
// layout: [cta][side(0N,1S,2W,3E)][field slot 0..4][2][43]
#define XLEN  (4*5*2*43)
__device__ float g_xch[NB*XLEN];
__device__ int   g_flag[NB*32];       // 128B padding per flag

#define XPTR(cta, side, f) (g_xch + (((cta)*4 + (side))*5 + (f))*86)
#define FLAG(cta) (g_flag[(cta)*32])

__global__ void k_init()
{
    int i = blockIdx.x*blockDim.x + threadIdx.x;
    if (i < NB) FLAG(i) = 0;
}

__device__ __forceinline__ float pml_b(int u)
{
    double d0 = 414.4653366865718;
    double lo = (20.0 - (double)u) / 20.0; lo = lo < 0.0 ? 0.0 : (lo > 1.0 ? 1.0 : lo);
    double hi = ((double)u - 319.0) / 20.0; hi = hi < 0.0 ? 0.0 : (hi > 1.0 ? 1.0 : hi);
    double mm = lo > hi ? lo : hi;
    return (float)exp(-d0 * mm * mm * 0.001);
}

__device__ __forceinline__ float2 lds2(const float* p){ return *(const float2*)p; }
__device__ __forceinline__ void   sts2(float* p, float2 v){ *(float2*)p = v; }

// ---------------- halo import (all threads, collective) ----------------
__device__ __forceinline__ void read_halos(float* F, int me, int f,
                                           int th, int tw,
                                           bool hN, bool hS, bool hW, bool hE,
                                           int tid, bool doNS, bool doWE)
{
    if (doNS && hN && tid < tw){
        const float* q = XPTR(me - TSX, 1, f);
        F[0*SP + tid + 2] = __ldcg(q + tid);
        F[1*SP + tid + 2] = __ldcg(q + 43 + tid);
    }
    if (doNS && hS && tid < tw){
        const float* q = XPTR(me + TSX, 0, f);
        F[(th+2)*SP + tid + 2] = __ldcg(q + tid);
        F[(th+3)*SP + tid + 2] = __ldcg(q + 43 + tid);
    }
    if (doWE && hW && tid < th){
        const float* q = XPTR(me - 1, 3, f);
        F[(tid+2)*SP + 0] = __ldcg(q + tid);
        F[(tid+2)*SP + 1] = __ldcg(q + 43 + tid);
    }
    if (doWE && hE && tid < th){
        const float* q = XPTR(me + 1, 2, f);
        F[(tid+2)*SP + tw + 2] = __ldcg(q + tid);
        F[(tid+2)*SP + tw + 3] = __ldcg(q + 43 + tid);
    }
}

// ---------------- pair physics ----------------
// pf bits: 0 = lane1 valid (full pair), 1 = y-PML, 2 = x-PML, [3:4] src lane
__device__ __forceinline__ void pairV(int o, float by, float bx0, float bx1, int pf, float srcamp,
    float* SVY, float* SVX, const float* SSYY, const float* SSXX, const float* SSXY,
    float* SMSYYY, float* SMSXYX, float* SMSXYY, float* SMSXXX, const float* SBUO,
    float2& vy_o, float2& vx_o)
{
    const bool pY = pf & 2, pX = pf & 4;
    float2 A = lds2(SSYY+o+SP), B = lds2(SSYY+o), C = lds2(SSYY+o+2*SP), D = lds2(SSYY+o-SP);
    float2 t1;
    t1.x = (C1F*(A.x-B.x) + C2F*(C.x-D.x))*INV_DX;
    t1.y = (C1F*(A.y-B.y) + C2F*(C.y-D.y))*INV_DX;
    if (pY){
        float2 m = lds2(SMSYYY+o);
        m.x = by*m.x + (by-1.0f)*t1.x;  m.y = by*m.y + (by-1.0f)*t1.y;
        sts2(SMSYYY+o, m);  t1.x += m.x;  t1.y += m.y;
    }
    float2 xa = lds2(SSXY+o-2), xb = lds2(SSXY+o), xc = lds2(SSXY+o+2);
    float2 t2;
    t2.x = (C1F*(xb.x-xa.y) + C2F*(xb.y-xa.x))*INV_DX;
    t2.y = (C1F*(xb.y-xb.x) + C2F*(xc.x-xa.y))*INV_DX;
    if (pX){
        float2 m = lds2(SMSXYX+o);
        m.x = bx0*m.x + (bx0-1.0f)*t2.x;  m.y = bx1*m.y + (bx1-1.0f)*t2.y;
        sts2(SMSXYX+o, m);  t2.x += m.x;  t2.y += m.y;
    }
    float2 buo = lds2(SBUO+o);
    float2 vy  = lds2(SVY+o);
    vy.x += DT_F*buo.x*(t1.x+t2.x);
    vy.y += DT_F*buo.y*(t1.y+t2.y);
    const int sm_ = (pf >> 3) & 3;
    if (sm_ == 1) vy.x += srcamp;
    if (sm_ == 2) vy.y += srcamp;
    float2 yb = lds2(SSXY+o-SP), yc = lds2(SSXY+o+SP), yd = lds2(SSXY+o-2*SP);
    float2 t3;
    t3.x = (C1F*(xb.x-yb.x) + C2F*(yc.x-yd.x))*INV_DX;
    t3.y = (C1F*(xb.y-yb.y) + C2F*(yc.y-yd.y))*INV_DX;
    if (pY){
        float2 m = lds2(SMSXYY+o);
        m.x = by*m.x + (by-1.0f)*t3.x;  m.y = by*m.y + (by-1.0f)*t3.y;
        sts2(SMSXYY+o, m);  t3.x += m.x;  t3.y += m.y;
    }
    float2 ba = lds2(SSXX+o-2), bb = lds2(SSXX+o), bc = lds2(SSXX+o+2);
    float2 t4;
    t4.x = (C1F*(bb.y-bb.x) + C2F*(bc.x-ba.y))*INV_DX;
    t4.y = (C1F*(bc.x-bb.y) + C2F*(bc.y-bb.x))*INV_DX;
    if (pX){
        float2 m = lds2(SMSXXX+o);
        m.x = bx0*m.x + (bx0-1.0f)*t4.x;  m.y = bx1*m.y + (bx1-1.0f)*t4.y;
        sts2(SMSXXX+o, m);  t4.x += m.x;  t4.y += m.y;
    }
    float2 vx = lds2(SVX+o);
    vx.x += DT_F*buo.x*(t3.x+t4.x);
    vx.y += DT_F*buo.y*(t3.y+t4.y);
    if (pf & 1){ sts2(SVY+o, vy); sts2(SVX+o, vx); }
    else       { SVY[o] = vy.x;  SVX[o] = vx.x; }
    vy_o = vy; vx_o = vx;
}

__device__ __forceinline__ void pairS(int o, float by, float bx0, float bx1, int pf,
    const float* SVY, const float* SVX, float* SSYY, float* SSXX, float* SSXY,
    float* SMVYY, float* SMVYX, float* SMVXY, float* SMVXX,
    const float* SLAM, const float* SLP2M, const float* SMU,
    float2& syy_o, float2& sxx_o, float2& sxy_o)
{
    const bool pY = pf & 2, pX = pf & 4;
    float2 vb  = lds2(SVY+o);
    float2 vd1 = lds2(SVY+o-SP), vu1 = lds2(SVY+o+SP), vd2 = lds2(SVY+o-2*SP);
    float2 dyy;
    dyy.x = (C1F*(vb.x-vd1.x) + C2F*(vu1.x-vd2.x))*INV_DX;
    dyy.y = (C1F*(vb.y-vd1.y) + C2F*(vu1.y-vd2.y))*INV_DX;
    if (pY){
        float2 m = lds2(SMVYY+o);
        m.x = by*m.x + (by-1.0f)*dyy.x;  m.y = by*m.y + (by-1.0f)*dyy.y;
        sts2(SMVYY+o, m);  dyy.x += m.x;  dyy.y += m.y;
    }
    float2 xa = lds2(SVX+o-2), xb = lds2(SVX+o), xc = lds2(SVX+o+2);
    float2 dxx;
    dxx.x = (C1F*(xb.x-xa.y) + C2F*(xb.y-xa.x))*INV_DX;
    dxx.y = (C1F*(xb.y-xb.x) + C2F*(xc.x-xa.y))*INV_DX;
    if (pX){
        float2 m = lds2(SMVXX+o);
        m.x = bx0*m.x + (bx0-1.0f)*dxx.x;  m.y = bx1*m.y + (bx1-1.0f)*dxx.y;
        sts2(SMVXX+o, m);  dxx.x += m.x;  dxx.y += m.y;
    }
    float2 lam = lds2(SLAM+o), lp2m = lds2(SLP2M+o);
    float2 syy = lds2(SSYY+o), sxx = lds2(SSXX+o);
    syy.x += DT_F*(lp2m.x*dyy.x + lam.x*dxx.x);
    syy.y += DT_F*(lp2m.y*dyy.y + lam.y*dxx.y);
    sxx.x += DT_F*(lp2m.x*dxx.x + lam.x*dyy.x);
    sxx.y += DT_F*(lp2m.y*dxx.y + lam.y*dyy.y);
    float2 va = lds2(SVY+o-2), vc = lds2(SVY+o+2);
    float2 dyx;
    dyx.x = (C1F*(vb.y-vb.x) + C2F*(vc.x-va.y))*INV_DX;
    dyx.y = (C1F*(vc.x-vb.y) + C2F*(vc.y-vb.x))*INV_DX;
    if (pX){
        float2 m = lds2(SMVYX+o);
        m.x = bx0*m.x + (bx0-1.0f)*dyx.x;  m.y = bx1*m.y + (bx1-1.0f)*dyx.y;
        sts2(SMVYX+o, m);  dyx.x += m.x;  dyx.y += m.y;
    }
    float2 ua = lds2(SVX+o+SP), uc = lds2(SVX+o+2*SP), ud = lds2(SVX+o-SP);
    float2 dxy;
    dxy.x = (C1F*(ua.x-xb.x) + C2F*(uc.x-ud.x))*INV_DX;
    dxy.y = (C1F*(ua.y-xb.y) + C2F*(uc.y-ud.y))*INV_DX;
    if (pY){
        float2 m = lds2(SMVXY+o);
        m.x = by*m.x + (by-1.0f)*dxy.x;  m.y = by*m.y + (by-1.0f)*dxy.y;
        sts2(SMVXY+o, m);  dxy.x += m.x;  dxy.y += m.y;
    }
    float2 mu  = lds2(SMU+o);
    float2 sxy = lds2(SSXY+o);
    sxy.x += DT_F*mu.x*(dyx.x+dxy.x);
    sxy.y += DT_F*mu.y*(dyx.y+dxy.y);
    if (pf & 1){ sts2(SSYY+o, syy); sts2(SSXX+o, sxx); sts2(SSXY+o, sxy); }
    else       { SSYY[o] = syy.x;  SSXX[o] = sxx.x;  SSXY[o] = sxy.x; }
    syy_o = syy; sxx_o = sxx; sxy_o = sxy;
}

__global__ void __launch_bounds__(NTHR, 3)
k_main(const float* __restrict__ lamb,
       const float* __restrict__ muv,
       const float* __restrict__ buov,
       const float* __restrict__ amp,    // [NSHOT,1,NT]
       const int*   __restrict__ sloc,   // [NSHOT,1,2]
       const int*   __restrict__ rloc,   // [NSHOT,NREC,2]
       float*       __restrict__ out)    // [NSHOT,NREC,NT]
{
    extern __shared__ float sm[];
    const int tid  = threadIdx.x;
    const int me   = blockIdx.x;
    const int shot = me / NTPS;
    const int tile = me - shot*NTPS;
    const int ty   = tile >> 3, tx = tile & 7;
    const int y0   = ty * TILEY, x0 = tx * TILEX;
    const int th   = (y0 + TILEY <= NYP) ? TILEY : (NYP - y0);
    const int tw   = (x0 + TILEX <= NXP) ? TILEX : (NXP - x0);
    const bool hN = (ty > 0), hS = (ty < TSY-1), hW = (tx > 0), hE = (tx < TSX-1);

    float* SVY    = sm + F_VY   *FSZ;
    float* SVX    = sm + F_VX   *FSZ;
    float* SSYY   = sm + F_SYY  *FSZ;
    float* SSXX   = sm + F_SXX  *FSZ;
    float* SSXY   = sm + F_SXY  *FSZ;
    float* SMVYY  = sm + F_MVYY *FSZ;
    float* SMVYX  = sm + F_MVYX *FSZ;
    float* SMVXY  = sm + F_MVXY *FSZ;
    float* SMVXX  = sm + F_MVXX *FSZ;
    float* SMSYYY = sm + F_MSYYY*FSZ;
    float* SMSXYX = sm + F_MSXYX*FSZ;
    float* SMSXYY = sm + F_MSXYY*FSZ;
    float* SMSXXX = sm + F_MSXXX*FSZ;
    float* SBUO   = sm + F_BUO  *FSZ;
    float* SLAM   = sm + F_LAM  *FSZ;
    float* SLP2M  = sm + F_LP2M *FSZ;
    float* SMU    = sm + F_MU   *FSZ;

    for (int i = tid; i < 13*FSZ; i += NTHR) sm[i] = 0.0f;

    for (int i = tid; i < FSZ; i += NTHR){
        int lr = i / SP, lc = i - lr*SP;
        int gy = y0 - 2 + lr, gx = x0 - 2 + lc;
        int iy = gy - PML_W; iy = iy < 0 ? 0 : (iy > NYI-1 ? NYI-1 : iy);
        int ix = gx - PML_W; ix = ix < 0 ? 0 : (ix > NXI-1 ? NXI-1 : ix);
        float l = lamb[iy*NXI + ix];
        float m = muv [iy*NXI + ix];
        SBUO[i]  = buov[iy*NXI + ix];
        SLAM[i]  = l;
        SLP2M[i] = l + 2.0f*m;
        SMU[i]   = m;
    }

    const int sy = sloc[shot*2 + 0] + PML_W;
    const int sx = sloc[shot*2 + 1] + PML_W;

    const int npr = (tw + 1) >> 1;

    // frame pair (<=1/thread) + export records
    int fo = -1; float fby = 1.0f, fbx0 = 1.0f, fbx1 = 1.0f; int fpf = 0;
    int fnrec = 0; int frec[4] = {0,0,0,0};   // packed: idx<<2 | lane<<1 | kind(0=NS,1=WE)
    {
        const int nframe = 4*npr + (th-4)*3;
        if (tid < nframe){
            int row, p;
            if (tid < 2*npr){ row = tid / npr; p = tid % npr; }
            else if (tid < 4*npr){ int q = tid - 2*npr; row = th-2 + q / npr; p = q % npr; }
            else { int q = tid - 4*npr; row = 2 + q / 3; int j = q % 3; p = (j == 0) ? 0 : (npr - 3 + j); }
            int lc = 2*p, gy = y0 + row, gx = x0 + lc;
            fo  = (row+2)*SP + (lc+2);
            fby = pml_b(gy); fbx0 = pml_b(gx);
            bool full = (lc + 1 < tw);
            fbx1 = full ? pml_b(gx+1) : 1.0f;
            fpf = (full ? 1 : 0)
                | ((fby  != 1.0f) ? 2 : 0)
                | (((fbx0 != 1.0f) || (fbx1 != 1.0f)) ? 4 : 0);
            if (gy == sy){
                if (sx == gx) fpf |= (1 << 3);
                else if (full && sx == gx+1) fpf |= (2 << 3);
            }
            for (int ln = 0; ln < 2; ln++){
                int col = lc + ln;
                if (col >= tw) break;
                if (ln == 1 && !(fpf & 1)) break;
                if (hN && row < 2)
                    frec[fnrec++] = (((((me*4 + 0)*5)*86) + row*43 + col) << 2) | (ln << 1) | 0;
                if (hS && row >= th-2)
                    frec[fnrec++] = (((((me*4 + 1)*5)*86) + (row-(th-2))*43 + col) << 2) | (ln << 1) | 0;
                if (hW && col < 2)
                    frec[fnrec++] = (((((me*4 + 2)*5)*86) + col*43 + row) << 2) | (ln << 1) | 1;
                if (hE && col >= tw-2)
                    frec[fnrec++] = (((((me*4 + 3)*5)*86) + (col-(tw-2))*43 + row) << 2) | (ln << 1) | 1;
            }
        }
    }

    // interior pairs: pair0 -> idx = tid; pair1 -> top tids (disabled when nint <= NTHR)
    int io[2] = {-1,-1}; float iby[2], ibx0[2], ibx1[2]; int ipf[2] = {0,0};
    {
        const int ppr = npr - 3;
        const int nint = (th-4) * ppr;
        const int n1 = nint - NTHR;
#pragma unroll
        for (int k = 0; k < 2; k++){
            iby[k] = 1.0f; ibx0[k] = 1.0f; ibx1[k] = 1.0f;
            int idx = (k == 0) ? tid : (tid + (n1 > 0 ? n1 : -NTHR));
            bool valid = (k == 0) ? (idx < nint) : (n1 > 0 && idx >= NTHR && idx < nint);
            if (valid){
                int row = 2 + idx / ppr, p = 1 + idx % ppr;
                int lc = 2*p, gy = y0 + row, gx = x0 + lc;
                io[k]   = (row+2)*SP + (lc+2);
                iby[k]  = pml_b(gy); ibx0[k] = pml_b(gx); ibx1[k] = pml_b(gx+1);
                ipf[k] = 1
                    | ((iby[k]  != 1.0f) ? 2 : 0)
                    | (((ibx0[k] != 1.0f) || (ibx1[k] != 1.0f)) ? 4 : 0);
                if (gy == sy){
                    if (sx == gx) ipf[k] |= (1 << 3);
                    else if (sx == gx+1) ipf[k] |= (2 << 3);
                }
            }
        }
    }

    // receiver ownership
    int rsoff = -1, rout = -1;
    if (tid < NSHOT*NREC){
        int rs = tid >> 5;
        int ry = rloc[tid*2 + 0] + PML_W;
        int rx = rloc[tid*2 + 1] + PML_W;
        if (rs == shot && ry >= y0 && ry < y0 + th && rx >= x0 && rx < x0 + tw){
            rsoff = (ry - y0 + 2)*SP + (rx - x0 + 2);
            rout  = tid*NT;
        }
    }
    __syncthreads();

    float2 dmy0, dmy1, dmy2;

    for (int t = 0; t < NT; t++){
        const float srcamp = amp[shot*NT + t];

        // ================= V phase =================
        if (fo >= 0){
            float2 vyv, vxv;
            pairV(fo, fby, fbx0, fbx1, fpf, srcamp, SVY, SVX, SSYY, SSXX, SSXY,
                  SMSYYY, SMSXYX, SMSXYY, SMSXXX, SBUO, vyv, vxv);
#pragma unroll
            for (int r = 0; r < 4; r++) if (r < fnrec){
                int pk = frec[r];
                int gi = pk >> 2;
                bool l1 = (pk & 2);
                g_xch[gi]      = l1 ? vyv.y : vyv.x;   // slot 0
                g_xch[gi + 86] = l1 ? vxv.y : vxv.x;   // slot 1
            }
        }
        __syncthreads();
        if (tid == 0){ __threadfence(); atomicExch(&FLAG(me), 2*t + 1); }

        if (io[0] >= 0)
            pairV(io[0], iby[0], ibx0[0], ibx1[0], ipf[0], srcamp, SVY, SVX, SSYY, SSXX, SSXY,
                  SMSYYY, SMSXYX, SMSXYY, SMSXXX, SBUO, dmy0, dmy1);

        if (tid == 32 && hN){ volatile int* f = &FLAG(me-TSX); while (*f < 2*t+1) {} }
        if (tid == 64 && hS){ volatile int* f = &FLAG(me+TSX); while (*f < 2*t+1) {} }
        if (tid == 96 && hW){ volatile int* f = &FLAG(me-1  ); while (*f < 2*t+1) {} }
        if (tid ==128 && hE){ volatile int* f = &FLAG(me+1  ); while (*f < 2*t+1) {} }
        __syncthreads();

        read_halos(SVY, me, 0, th, tw, hN, hS, hW, hE, tid, true, true);
        read_halos(SVX, me, 1, th, tw, hN, hS, hW, hE, tid, true, true);
        if (io[1] >= 0)
            pairV(io[1], iby[1], ibx0[1], ibx1[1], ipf[1], srcamp, SVY, SVX, SSYY, SSXX, SSXY,
                  SMSYYY, SMSXYX, SMSXYY, SMSXXX, SBUO, dmy0, dmy1);
        __syncthreads();

        if (rout >= 0) out[rout + t] = SVY[rsoff];

        // ================= S phase =================
        if (fo >= 0){
            float2 syyv, sxxv, sxyv;
            pairS(fo, fby, fbx0, fbx1, fpf, SVY, SVX, SSYY, SSXX, SSXY,
                  SMVYY, SMVYX, SMVXY, SMVXX, SLAM, SLP2M, SMU, syyv, sxxv, sxyv);
#pragma unroll
            for (int r = 0; r < 4; r++) if (r < fnrec){
                int pk = frec[r];
                int gi = pk >> 2;
                bool l1 = (pk & 2);
                float sxyl = l1 ? sxyv.y : sxyv.x;
                if ((pk & 1) == 0){                      // NS side: syy (2) + sxy (4)
                    g_xch[gi + 172] = l1 ? syyv.y : syyv.x;
                    g_xch[gi + 344] = sxyl;
                } else {                                 // WE side: sxx (3) + sxy (4)
                    g_xch[gi + 258] = l1 ? sxxv.y : sxxv.x;
                    g_xch[gi + 344] = sxyl;
                }
            }
        }
        __syncthreads();
        if (tid == 0){ __threadfence(); atomicExch(&FLAG(me), 2*t + 2); }

        if (io[0] >= 0)
            pairS(io[0], iby[0], ibx0[0], ibx1[0], ipf[0], SVY, SVX, SSYY, SSXX, SSXY,
                  SMVYY, SMVYX, SMVXY, SMVXX, SLAM, SLP2M, SMU, dmy0, dmy1, dmy2);

        if (tid == 32 && hN){ volatile int* f = &FLAG(me-TSX); while (*f < 2*t+2) {} }
        if (tid == 64 && hS){ volatile int* f = &FLAG(me+TSX); while (*f < 2*t+2) {} }
        if (tid == 96 && hW){ volatile int* f = &FLAG(me-1  ); while (*f < 2*t+2) {} }
        if (tid ==128 && hE){ volatile int* f = &FLAG(me+1  ); while (*f < 2*t+2) {} }
        __syncthreads();

        read_halos(SSYY, me, 2, th, tw, hN, hS, hW, hE, tid, true,  false);
        read_halos(SSXX, me, 3, th, tw, hN, hS, hW, hE, tid, false, true );
        read_halos(SSXY, me, 4, th, tw, hN, hS, hW, hE, tid, true,  true );
        if (io[1] >= 0)
            pairS(io[1], iby[1], ibx0[1], ibx1[1], ipf[1], SVY, SVX, SSYY, SSXX, SSXY,
                  SMVYY, SMVYX, SMVXY, SMVXX, SLAM, SLP2M, SMU, dmy0, dmy1, dmy2);
        __syncthreads();
    }
}

// ---------------- launch ----------------
extern "C" void kernel_launch(void* const* d_in, const int* in_sizes, int n_in,
                              void* d_out, int out_size)
{
    const float* lamb = (const float*)d_in[0];
    const float* mu   = (const float*)d_in[1];
    const float* buo  = (const float*)d_in[2];
    const float* amp  = (const float*)d_in[3];
    const int*   sloc = (const int*)  d_in[4];
    const int*   rloc = (const int*)  d_in[5];
    float* out = (float*)d_out;

    cudaFuncSetAttribute(k_main, cudaFuncAttributeMaxDynamicSharedMemorySize, SMEM_BYTES);

    k_init<<<1, 512>>>();
    k_main<<<NB, NTHR, SMEM_BYTES>>>(lamb, mu, buo, amp, sloc, rloc, out);
}

// round 17
// speedup vs baseline: 1.7198x; 1.2260x over previous
#include <cuda_runtime.h>
#include <math.h>

// ---------------- problem constants ----------------
#define NYI   300
#define NXI   300
#define PML_W 20
#define NYP   340
#define NXP   340
#define NT    128
#define NSHOT 2
#define NREC  32
#define DT_F    0.001f
#define INV_DX  0.2f
#define C1F     1.125f
#define C2F     (-1.0f/24.0f)

// ---------------- tiling: 16x8 tiles per shot, 2 CTAs per SM ----------------
#define TSY   16
#define TSX   8
#define TILEY 22
#define TILEX 43
#define NB    (NSHOT*TSY*TSX)         // 256 CTAs
#define NTHR  256
#define SP    52                      // even smem row pitch (8B pair alignment)
#define SROWS (TILEY+4)               // 26
#define FSZ   (SROWS*SP)              // 1352 floats per field
#define NFS   17
#define SMEM_BYTES (NFS*FSZ*4)        // 91936 B (2 per SM)

enum {F_VY=0,F_VX,F_SYY,F_SXX,F_SXY,F_MVYY,F_MVYX,F_MVXY,F_MVXX,
      F_MSYYY,F_MSXYX,F_MSXYY,F_MSXXX,F_BUO,F_LAM,F_LP2M,F_MU};

// ---------------- exchange buffers ----------------
// layout: [cta][side(0N,1S,2W,3E)][field slot 0..4][2][43]
#define XLEN  (4*5*2*43)
__device__ float g_xch[NB*XLEN];
__device__ int   g_flag[NB*32];       // 128B padding per flag

#define XPTR(cta, side, f) (g_xch + (((cta)*4 + (side))*5 + (f))*86)
#define FLAG(cta) (g_flag[(cta)*32])

__global__ void k_init()
{
    if (threadIdx.x < NB) FLAG(threadIdx.x) = 0;
}

__device__ __forceinline__ float pml_b(int u)
{
    double d0 = 414.4653366865718;
    double lo = (20.0 - (double)u) / 20.0; lo = lo < 0.0 ? 0.0 : (lo > 1.0 ? 1.0 : lo);
    double hi = ((double)u - 319.0) / 20.0; hi = hi < 0.0 ? 0.0 : (hi > 1.0 ? 1.0 : hi);
    double mm = lo > hi ? lo : hi;
    return (float)exp(-d0 * mm * mm * 0.001);
}

__device__ __forceinline__ float2 lds2(const float* p){ return *(const float2*)p; }
__device__ __forceinline__ void   sts2(float* p, float2 v){ *(float2*)p = v; }

// ---------------- halo import (all threads, collective; behind __syncthreads) ----------------
__device__ __forceinline__ void read_halos(float* F, int me, int f,
                                           int th, int tw,
                                           bool hN, bool hS, bool hW, bool hE,
                                           int tid, bool doNS, bool doWE)
{
    if (doNS && hN && tid < tw){
        const float* q = XPTR(me - TSX, 1, f);
        F[0*SP + tid + 2] = __ldcg(q + tid);
        F[1*SP + tid + 2] = __ldcg(q + 43 + tid);
    }
    if (doNS && hS && tid < tw){
        const float* q = XPTR(me + TSX, 0, f);
        F[(th+2)*SP + tid + 2] = __ldcg(q + tid);
        F[(th+3)*SP + tid + 2] = __ldcg(q + 43 + tid);
    }
    if (doWE && hW && tid < th){
        const float* q = XPTR(me - 1, 3, f);
        F[(tid+2)*SP + 0] = __ldcg(q + tid);
        F[(tid+2)*SP + 1] = __ldcg(q + 43 + tid);
    }
    if (doWE && hE && tid < th){
        const float* q = XPTR(me + 1, 2, f);
        F[(tid+2)*SP + tw + 2] = __ldcg(q + tid);
        F[(tid+2)*SP + tw + 3] = __ldcg(q + 43 + tid);
    }
}

// ---------------- pair physics ----------------
// pf bits: 0 = lane1 valid (full pair), 1 = y-PML, 2 = x-PML, [3:4] src lane
__device__ __forceinline__ void pairV(int o, float by, float bx0, float bx1, int pf, float srcamp,
    float* SVY, float* SVX, const float* SSYY, const float* SSXX, const float* SSXY,
    float* SMSYYY, float* SMSXYX, float* SMSXYY, float* SMSXXX, const float* SBUO,
    float2& vy_o, float2& vx_o)
{
    const bool pY = pf & 2, pX = pf & 4;
    float2 A = lds2(SSYY+o+SP), B = lds2(SSYY+o), C = lds2(SSYY+o+2*SP), D = lds2(SSYY+o-SP);
    float2 t1;
    t1.x = (C1F*(A.x-B.x) + C2F*(C.x-D.x))*INV_DX;
    t1.y = (C1F*(A.y-B.y) + C2F*(C.y-D.y))*INV_DX;
    if (pY){
        float2 m = lds2(SMSYYY+o);
        m.x = by*m.x + (by-1.0f)*t1.x;  m.y = by*m.y + (by-1.0f)*t1.y;
        sts2(SMSYYY+o, m);  t1.x += m.x;  t1.y += m.y;
    }
    float2 xa = lds2(SSXY+o-2), xb = lds2(SSXY+o), xc = lds2(SSXY+o+2);
    float2 t2;
    t2.x = (C1F*(xb.x-xa.y) + C2F*(xb.y-xa.x))*INV_DX;
    t2.y = (C1F*(xb.y-xb.x) + C2F*(xc.x-xa.y))*INV_DX;
    if (pX){
        float2 m = lds2(SMSXYX+o);
        m.x = bx0*m.x + (bx0-1.0f)*t2.x;  m.y = bx1*m.y + (bx1-1.0f)*t2.y;
        sts2(SMSXYX+o, m);  t2.x += m.x;  t2.y += m.y;
    }
    float2 buo = lds2(SBUO+o);
    float2 vy  = lds2(SVY+o);
    vy.x += DT_F*buo.x*(t1.x+t2.x);
    vy.y += DT_F*buo.y*(t1.y+t2.y);
    const int sm_ = (pf >> 3) & 3;
    if (sm_ == 1) vy.x += srcamp;
    if (sm_ == 2) vy.y += srcamp;
    float2 yb = lds2(SSXY+o-SP), yc = lds2(SSXY+o+SP), yd = lds2(SSXY+o-2*SP);
    float2 t3;
    t3.x = (C1F*(xb.x-yb.x) + C2F*(yc.x-yd.x))*INV_DX;
    t3.y = (C1F*(xb.y-yb.y) + C2F*(yc.y-yd.y))*INV_DX;
    if (pY){
        float2 m = lds2(SMSXYY+o);
        m.x = by*m.x + (by-1.0f)*t3.x;  m.y = by*m.y + (by-1.0f)*t3.y;
        sts2(SMSXYY+o, m);  t3.x += m.x;  t3.y += m.y;
    }
    float2 ba = lds2(SSXX+o-2), bb = lds2(SSXX+o), bc = lds2(SSXX+o+2);
    float2 t4;
    t4.x = (C1F*(bb.y-bb.x) + C2F*(bc.x-ba.y))*INV_DX;
    t4.y = (C1F*(bc.x-bb.y) + C2F*(bc.y-bb.x))*INV_DX;
    if (pX){
        float2 m = lds2(SMSXXX+o);
        m.x = bx0*m.x + (bx0-1.0f)*t4.x;  m.y = bx1*m.y + (bx1-1.0f)*t4.y;
        sts2(SMSXXX+o, m);  t4.x += m.x;  t4.y += m.y;
    }
    float2 vx = lds2(SVX+o);
    vx.x += DT_F*buo.x*(t3.x+t4.x);
    vx.y += DT_F*buo.y*(t3.y+t4.y);
    if (pf & 1){ sts2(SVY+o, vy); sts2(SVX+o, vx); }
    else       { SVY[o] = vy.x;  SVX[o] = vx.x; }
    vy_o = vy; vx_o = vx;
}

__device__ __forceinline__ void pairS(int o, float by, float bx0, float bx1, int pf,
    const float* SVY, const float* SVX, float* SSYY, float* SSXX, float* SSXY,
    float* SMVYY, float* SMVYX, float* SMVXY, float* SMVXX,
    const float* SLAM, const float* SLP2M, const float* SMU,
    float2& syy_o, float2& sxx_o, float2& sxy_o)
{
    const bool pY = pf & 2, pX = pf & 4;
    float2 vb  = lds2(SVY+o);
    float2 vd1 = lds2(SVY+o-SP), vu1 = lds2(SVY+o+SP), vd2 = lds2(SVY+o-2*SP);
    float2 dyy;
    dyy.x = (C1F*(vb.x-vd1.x) + C2F*(vu1.x-vd2.x))*INV_DX;
    dyy.y = (C1F*(vb.y-vd1.y) + C2F*(vu1.y-vd2.y))*INV_DX;
    if (pY){
        float2 m = lds2(SMVYY+o);
        m.x = by*m.x + (by-1.0f)*dyy.x;  m.y = by*m.y + (by-1.0f)*dyy.y;
        sts2(SMVYY+o, m);  dyy.x += m.x;  dyy.y += m.y;
    }
    float2 xa = lds2(SVX+o-2), xb = lds2(SVX+o), xc = lds2(SVX+o+2);
    float2 dxx;
    dxx.x = (C1F*(xb.x-xa.y) + C2F*(xb.y-xa.x))*INV_DX;
    dxx.y = (C1F*(xb.y-xb.x) + C2F*(xc.x-xa.y))*INV_DX;
    if (pX){
        float2 m = lds2(SMVXX+o);
        m.x = bx0*m.x + (bx0-1.0f)*dxx.x;  m.y = bx1*m.y + (bx1-1.0f)*dxx.y;
        sts2(SMVXX+o, m);  dxx.x += m.x;  dxx.y += m.y;
    }
    float2 lam = lds2(SLAM+o), lp2m = lds2(SLP2M+o);
    float2 syy = lds2(SSYY+o), sxx = lds2(SSXX+o);
    syy.x += DT_F*(lp2m.x*dyy.x + lam.x*dxx.x);
    syy.y += DT_F*(lp2m.y*dyy.y + lam.y*dxx.y);
    sxx.x += DT_F*(lp2m.x*dxx.x + lam.x*dyy.x);
    sxx.y += DT_F*(lp2m.y*dxx.y + lam.y*dyy.y);
    float2 va = lds2(SVY+o-2), vc = lds2(SVY+o+2);
    float2 dyx;
    dyx.x = (C1F*(vb.y-vb.x) + C2F*(vc.x-va.y))*INV_DX;
    dyx.y = (C1F*(vc.x-vb.y) + C2F*(vc.y-vb.x))*INV_DX;
    if (pX){
        float2 m = lds2(SMVYX+o);
        m.x = bx0*m.x + (bx0-1.0f)*dyx.x;  m.y = bx1*m.y + (bx1-1.0f)*dyx.y;
        sts2(SMVYX+o, m);  dyx.x += m.x;  dyx.y += m.y;
    }
    float2 ua = lds2(SVX+o+SP), uc = lds2(SVX+o+2*SP), ud = lds2(SVX+o-SP);
    float2 dxy;
    dxy.x = (C1F*(ua.x-xb.x) + C2F*(uc.x-ud.x))*INV_DX;
    dxy.y = (C1F*(ua.y-xb.y) + C2F*(uc.y-ud.y))*INV_DX;
    if (pY){
        float2 m = lds2(SMVXY+o);
        m.x = by*m.x + (by-1.0f)*dxy.x;  m.y = by*m.y + (by-1.0f)*dxy.y;
        sts2(SMVXY+o, m);  dxy.x += m.x;  dxy.y += m.y;
    }
    float2 mu  = lds2(SMU+o);
    float2 sxy = lds2(SSXY+o);
    sxy.x += DT_F*mu.x*(dyx.x+dxy.x);
    sxy.y += DT_F*mu.y*(dyx.y+dxy.y);
    if (pf & 1){ sts2(SSYY+o, syy); sts2(SSXX+o, sxx); sts2(SSXY+o, sxy); }
    else       { SSYY[o] = syy.x;  SSXX[o] = sxx.x;  SSXY[o] = sxy.x; }
    syy_o = syy; sxx_o = sxx; sxy_o = sxy;
}

__global__ void __launch_bounds__(NTHR, 2)
k_main(const float* __restrict__ lamb,
       const float* __restrict__ muv,
       const float* __restrict__ buov,
       const float* __restrict__ amp,    // [NSHOT,1,NT]
       const int*   __restrict__ sloc,   // [NSHOT,1,2]
       const int*   __restrict__ rloc,   // [NSHOT,NREC,2]
       float*       __restrict__ out)    // [NSHOT,NREC,NT]
{
    extern __shared__ float sm[];
    const int tid  = threadIdx.x;
    const int me   = blockIdx.x;
    const int shot = me >> 7;
    const int tile = me & 127;
    const int ty   = tile >> 3, tx = tile & 7;
    const int y0   = ty * TILEY, x0 = tx * TILEX;
    const int th   = (y0 + TILEY <= NYP) ? TILEY : (NYP - y0);
    const int tw   = (x0 + TILEX <= NXP) ? TILEX : (NXP - x0);
    const bool hN = (ty > 0), hS = (ty < TSY-1), hW = (tx > 0), hE = (tx < TSX-1);

    float* SVY    = sm + F_VY   *FSZ;
    float* SVX    = sm + F_VX   *FSZ;
    float* SSYY   = sm + F_SYY  *FSZ;
    float* SSXX   = sm + F_SXX  *FSZ;
    float* SSXY   = sm + F_SXY  *FSZ;
    float* SMVYY  = sm + F_MVYY *FSZ;
    float* SMVYX  = sm + F_MVYX *FSZ;
    float* SMVXY  = sm + F_MVXY *FSZ;
    float* SMVXX  = sm + F_MVXX *FSZ;
    float* SMSYYY = sm + F_MSYYY*FSZ;
    float* SMSXYX = sm + F_MSXYX*FSZ;
    float* SMSXYY = sm + F_MSXYY*FSZ;
    float* SMSXXX = sm + F_MSXXX*FSZ;
    float* SBUO   = sm + F_BUO  *FSZ;
    float* SLAM   = sm + F_LAM  *FSZ;
    float* SLP2M  = sm + F_LP2M *FSZ;
    float* SMU    = sm + F_MU   *FSZ;

    for (int i = tid; i < 13*FSZ; i += NTHR) sm[i] = 0.0f;

    for (int i = tid; i < FSZ; i += NTHR){
        int lr = i / SP, lc = i - lr*SP;
        int gy = y0 - 2 + lr, gx = x0 - 2 + lc;
        int iy = gy - PML_W; iy = iy < 0 ? 0 : (iy > NYI-1 ? NYI-1 : iy);
        int ix = gx - PML_W; ix = ix < 0 ? 0 : (ix > NXI-1 ? NXI-1 : ix);
        float l = lamb[iy*NXI + ix];
        float m = muv [iy*NXI + ix];
        SBUO[i]  = buov[iy*NXI + ix];
        SLAM[i]  = l;
        SLP2M[i] = l + 2.0f*m;
        SMU[i]   = m;
    }

    const int sy = sloc[shot*2 + 0] + PML_W;
    const int sx = sloc[shot*2 + 1] + PML_W;

    const int npr = (tw + 1) >> 1;

    // spinner duty (R11 scheme): tid 32=N, 64=S, 96=W, 128=E
    const bool spN = (tid == 32  && hN), spS = (tid == 64  && hS);
    const bool spW = (tid == 96  && hW), spE = (tid == 128 && hE);
    int snb = 0;
    if (spN) snb = me - TSX;
    if (spS) snb = me + TSX;
    if (spW) snb = me - 1;
    if (spE) snb = me + 1;
    const bool sp = spN | spS | spW | spE;

    // frame pair (<=1/thread) + export records
    int fo = -1; float fby = 1.0f, fbx0 = 1.0f, fbx1 = 1.0f; int fpf = 0;
    int fnrec = 0; int frec[4] = {0,0,0,0};   // packed: idx<<2 | lane<<1 | kind(0=NS,1=WE)
    {
        const int nframe = 4*npr + (th-4)*3;
        if (tid < nframe){
            int row, p;
            if (tid < 2*npr){ row = tid / npr; p = tid % npr; }
            else if (tid < 4*npr){ int q = tid - 2*npr; row = th-2 + q / npr; p = q % npr; }
            else { int q = tid - 4*npr; row = 2 + q / 3; int j = q % 3; p = (j == 0) ? 0 : (npr - 3 + j); }
            int lc = 2*p, gy = y0 + row, gx = x0 + lc;
            fo  = (row+2)*SP + (lc+2);
            fby = pml_b(gy); fbx0 = pml_b(gx);
            bool full = (lc + 1 < tw);
            fbx1 = full ? pml_b(gx+1) : 1.0f;
            fpf = (full ? 1 : 0)
                | ((fby  != 1.0f) ? 2 : 0)
                | (((fbx0 != 1.0f) || (fbx1 != 1.0f)) ? 4 : 0);
            if (gy == sy){
                if (sx == gx) fpf |= (1 << 3);
                else if (full && sx == gx+1) fpf |= (2 << 3);
            }
            for (int ln = 0; ln < 2; ln++){
                int col = lc + ln;
                if (col >= tw) break;
                if (ln == 1 && !(fpf & 1)) break;
                if (hN && row < 2)
                    frec[fnrec++] = (((((me*4 + 0)*5)*86) + row*43 + col) << 2) | (ln << 1) | 0;
                if (hS && row >= th-2)
                    frec[fnrec++] = (((((me*4 + 1)*5)*86) + (row-(th-2))*43 + col) << 2) | (ln << 1) | 0;
                if (hW && col < 2)
                    frec[fnrec++] = (((((me*4 + 2)*5)*86) + col*43 + row) << 2) | (ln << 1) | 1;
                if (hE && col >= tw-2)
                    frec[fnrec++] = (((((me*4 + 3)*5)*86) + (col-(tw-2))*43 + row) << 2) | (ln << 1) | 1;
            }
        }
    }

    // interior pairs: pair0 -> idx = tid; pair1 -> top tids via idx = tid + n1
    int io[2] = {-1,-1}; float iby[2], ibx0[2], ibx1[2]; int ipf[2] = {0,0};
    {
        const int ppr = npr - 3;
        const int nint = (th-4) * ppr;
        const int n1 = nint - NTHR;
#pragma unroll
        for (int k = 0; k < 2; k++){
            iby[k] = 1.0f; ibx0[k] = 1.0f; ibx1[k] = 1.0f;
            int idx = (k == 0) ? tid : (tid + (n1 > 0 ? n1 : -NTHR));
            bool valid = (k == 0) ? (idx < nint) : (n1 > 0 && idx >= NTHR && idx < nint);
            if (valid){
                int row = 2 + idx / ppr, p = 1 + idx % ppr;
                int lc = 2*p, gy = y0 + row, gx = x0 + lc;
                io[k]   = (row+2)*SP + (lc+2);
                iby[k]  = pml_b(gy); ibx0[k] = pml_b(gx); ibx1[k] = pml_b(gx+1);
                ipf[k] = 1
                    | ((iby[k]  != 1.0f) ? 2 : 0)
                    | (((ibx0[k] != 1.0f) || (ibx1[k] != 1.0f)) ? 4 : 0);
                if (gy == sy){
                    if (sx == gx) ipf[k] |= (1 << 3);
                    else if (sx == gx+1) ipf[k] |= (2 << 3);
                }
            }
        }
    }

    // receiver ownership
    int rsoff = -1, rout = -1;
    if (tid < NSHOT*NREC){
        int rs = tid >> 5;
        int ry = rloc[tid*2 + 0] + PML_W;
        int rx = rloc[tid*2 + 1] + PML_W;
        if (rs == shot && ry >= y0 && ry < y0 + th && rx >= x0 && rx < x0 + tw){
            rsoff = (ry - y0 + 2)*SP + (rx - x0 + 2);
            rout  = tid*NT;
        }
    }
    __syncthreads();

    float2 dmy0, dmy1, dmy2;

    for (int t = 0; t < NT; t++){
        const float srcamp = amp[shot*NT + t];

        // ================= V phase =================
        if (fo >= 0){
            float2 vyv, vxv;
            pairV(fo, fby, fbx0, fbx1, fpf, srcamp, SVY, SVX, SSYY, SSXX, SSXY,
                  SMSYYY, SMSXYX, SMSXYY, SMSXXX, SBUO, vyv, vxv);
#pragma unroll
            for (int r = 0; r < 4; r++) if (r < fnrec){
                int pk = frec[r];
                int gi = pk >> 2;
                bool l1 = (pk & 2);
                g_xch[gi]      = l1 ? vyv.y : vyv.x;   // slot 0
                g_xch[gi + 86] = l1 ? vxv.y : vxv.x;   // slot 1
            }
        }
        __syncthreads();                                   // barA
        if (tid == 0){ __threadfence(); atomicExch(&FLAG(me), 2*t + 1); }

        const int eV = 2*t + 1;
        // early probe by spinner threads (overlaps L2 round trip with pair0)
        int pr = 0x80000000;
        if (sp) pr = *(volatile int*)&FLAG(snb);

        if (io[0] >= 0)
            pairV(io[0], iby[0], ibx0[0], ibx1[0], ipf[0], srcamp, SVY, SVX, SSYY, SSXX, SSXY,
                  SMSYYY, SMSXYX, SMSXYY, SMSXXX, SBUO, dmy0, dmy1);

        if (sp && pr < eV){ volatile int* f = &FLAG(snb); while (*f < eV) {} }
        __syncthreads();                                   // barB

        read_halos(SVY, me, 0, th, tw, hN, hS, hW, hE, tid, true, true);
        read_halos(SVX, me, 1, th, tw, hN, hS, hW, hE, tid, true, true);
        if (io[1] >= 0)
            pairV(io[1], iby[1], ibx0[1], ibx1[1], ipf[1], srcamp, SVY, SVX, SSYY, SSXX, SSXY,
                  SMSYYY, SMSXYX, SMSXYY, SMSXXX, SBUO, dmy0, dmy1);
        __syncthreads();                                   // barC

        if (rout >= 0) out[rout + t] = SVY[rsoff];

        // ================= S phase =================
        if (fo >= 0){
            float2 syyv, sxxv, sxyv;
            pairS(fo, fby, fbx0, fbx1, fpf, SVY, SVX, SSYY, SSXX, SSXY,
                  SMVYY, SMVYX, SMVXY, SMVXX, SLAM, SLP2M, SMU, syyv, sxxv, sxyv);
#pragma unroll
            for (int r = 0; r < 4; r++) if (r < fnrec){
                int pk = frec[r];
                int gi = pk >> 2;
                bool l1 = (pk & 2);
                float sxyl = l1 ? sxyv.y : sxyv.x;
                if ((pk & 1) == 0){                      // NS side: syy (2) + sxy (4)
                    g_xch[gi + 172] = l1 ? syyv.y : syyv.x;
                    g_xch[gi + 344] = sxyl;
                } else {                                 // WE side: sxx (3) + sxy (4)
                    g_xch[gi + 258] = l1 ? sxxv.y : sxxv.x;
                    g_xch[gi + 344] = sxyl;
                }
            }
        }
        __syncthreads();                                   // barA
        if (tid == 0){ __threadfence(); atomicExch(&FLAG(me), 2*t + 2); }

        const int eS = 2*t + 2;
        pr = 0x80000000;
        if (sp) pr = *(volatile int*)&FLAG(snb);

        if (io[0] >= 0)
            pairS(io[0], iby[0], ibx0[0], ibx1[0], ipf[0], SVY, SVX, SSYY, SSXX, SSXY,
                  SMVYY, SMVYX, SMVXY, SMVXX, SLAM, SLP2M, SMU, dmy0, dmy1, dmy2);

        if (sp && pr < eS){ volatile int* f = &FLAG(snb); while (*f < eS) {} }
        __syncthreads();                                   // barB

        read_halos(SSYY, me, 2, th, tw, hN, hS, hW, hE, tid, true,  false);
        read_halos(SSXX, me, 3, th, tw, hN, hS, hW, hE, tid, false, true );
        read_halos(SSXY, me, 4, th, tw, hN, hS, hW, hE, tid, true,  true );
        if (io[1] >= 0)
            pairS(io[1], iby[1], ibx0[1], ibx1[1], ipf[1], SVY, SVX, SSYY, SSXX, SSXY,
                  SMVYY, SMVYX, SMVXY, SMVXX, SLAM, SLP2M, SMU, dmy0, dmy1, dmy2);
        __syncthreads();                                   // barC
    }
}

// ---------------- launch ----------------
extern "C" void kernel_launch(void* const* d_in, const int* in_sizes, int n_in,
                              void* d_out, int out_size)
{
    const float* lamb = (const float*)d_in[0];
    const float* mu   = (const float*)d_in[1];
    const float* buo  = (const float*)d_in[2];
    const float* amp  = (const float*)d_in[3];
    const int*   sloc = (const int*)  d_in[4];
    const int*   rloc = (const int*)  d_in[5];
    float* out = (float*)d_out;

    cudaFuncSetAttribute(k_main, cudaFuncAttributeMaxDynamicSharedMemorySize, SMEM_BYTES);

    k_init<<<1, 256>>>();
    k_main<<<NB, NTHR, SMEM_BYTES>>>(lamb, mu, buo, amp, sloc, rloc, out);
}